// round 7
// baseline (speedup 1.0000x reference)
#include <cuda_runtime.h>
#include <cuda_bf16.h>

#define IMG_H 480
#define IMG_W 640
#define HW (IMG_H * IMG_W)          // 307200
#define CHW (3 * HW)
#define QPP (HW / 4)                // float4 quads per plane = 76800
#define RED_THREADS 256
#define RED_QPT 4
#define RED_BLOCKS_PER_PLANE (QPP / (RED_THREADS * RED_QPT))   // 75, exact
#define MAIN_THREADS 256
#define MAIN_QPT 2
#define MAIN_BLOCKS_PER_PLANE (QPP / (MAIN_THREADS * MAIN_QPT)) // 150, exact
#define MAX_B 64

// Scratch (device globals per harness rules).
// g_graysum starts zeroed (static init); the LAST main-kernel block to check
// in (after every block has read the mean) re-zeroes it for the next replay.
__device__ float g_graysum[MAX_B];
__device__ unsigned g_fin = 0;

__device__ __forceinline__ float quad_gray(const float4& r4, const float4& g4,
                                           const float4& b4, float B) {
    float s = 0.0f;
    float r, g, bl;
    #define ACC(comp) \
        r = __saturatef(r4.comp * B); \
        g = __saturatef(g4.comp * B); \
        bl = __saturatef(b4.comp * B); \
        s += 0.299f * r + 0.587f * g + 0.114f * bl;
    ACC(x) ACC(y) ACC(z) ACC(w)
    #undef ACC
    return s;
}

// Pass 1: per-batch gray sums, 4 quads/thread in two pipelined halves.
// Default cache policy so x becomes L2-resident for pass 2.
__global__ void __launch_bounds__(RED_THREADS)
cr_reduce_kernel(const float* __restrict__ x, const float* __restrict__ bf) {
    const int b = blockIdx.y;
    const int q0 = blockIdx.x * (RED_THREADS * RED_QPT) + threadIdx.x;
    const float4* base = (const float4*)(x + (size_t)b * CHW);
    const float B = bf[b];

    float s;
    {   // half 1: quads q0, q0+256 (6 loads in flight)
        const int qa = q0, qb = q0 + RED_THREADS;
        float4 r0 = base[qa], g0 = base[qa + QPP], c0 = base[qa + 2 * QPP];
        float4 r1 = base[qb], g1 = base[qb + QPP], c1 = base[qb + 2 * QPP];
        s = quad_gray(r0, g0, c0, B) + quad_gray(r1, g1, c1, B);
    }
    {   // half 2: quads q0+512, q0+768
        const int qa = q0 + 2 * RED_THREADS, qb = q0 + 3 * RED_THREADS;
        float4 r0 = base[qa], g0 = base[qa + QPP], c0 = base[qa + 2 * QPP];
        float4 r1 = base[qb], g1 = base[qb + QPP], c1 = base[qb + 2 * QPP];
        s += quad_gray(r0, g0, c0, B) + quad_gray(r1, g1, c1, B);
    }

    #pragma unroll
    for (int o = 16; o > 0; o >>= 1)
        s += __shfl_xor_sync(0xFFFFFFFFu, s, o);

    __shared__ float warp_s[RED_THREADS / 32];
    const int lane = threadIdx.x & 31;
    const int wid = threadIdx.x >> 5;
    if (lane == 0) warp_s[wid] = s;
    __syncthreads();
    if (wid == 0) {
        s = (lane < RED_THREADS / 32) ? warp_s[lane] : 0.0f;
        #pragma unroll
        for (int o = 4; o > 0; o >>= 1)
            s += __shfl_xor_sync(0xFFFFFFFFu, s, o);
        if (lane == 0) atomicAdd(&g_graysum[b], s);
    }
}

// Branchless fused pipeline. cm = (1-C)*mean is batch-uniform (hoisted).
__device__ __forceinline__ void process_px(float& r, float& g, float& b,
                                           float Bf, float Cf, float cm,
                                           float Sf, float hfv) {
    // brightness
    r = __saturatef(r * Bf);
    g = __saturatef(g * Bf);
    b = __saturatef(b * Bf);
    // contrast
    r = __saturatef(fmaf(Cf, r, cm));
    g = __saturatef(fmaf(Cf, g, cm));
    b = __saturatef(fmaf(Cf, b, cm));
    // saturation
    const float gray = 0.299f * r + 0.587f * g + 0.114f * b;
    const float sm = (1.0f - Sf) * gray;
    r = __saturatef(fmaf(Sf, r, sm));
    g = __saturatef(fmaf(Sf, g, sm));
    b = __saturatef(fmaf(Sf, b, sm));
    // hue rotation — branchless (v*s == chroma identically; continuous form
    // reproduces the reference case table exactly).
    const float maxc = fmaxf(r, fmaxf(g, b));
    const float minc = fminf(r, fminf(g, b));
    const float c = maxc - minc;
    const float crd = (c == 0.0f) ? 1.0f : c;
    float num, base;
    if (maxc == r)      { num = g - b; base = 0.0f; }   // priority order kept
    else if (maxc == g) { num = b - r; base = 2.0f; }
    else                { num = r - g; base = 4.0f; }
    float h = (base + __fdividef(num, crd)) * (1.0f / 6.0f);
    h -= floorf(h);          // positive mod 1 (jnp semantics)
    h += hfv;
    h -= floorf(h);
    const float i6 = h * 6.0f;               // in [0, 6]
    float kr = i6 + 5.0f; kr = (kr >= 6.0f) ? kr - 6.0f : kr;
    float kg = i6 + 3.0f; kg = (kg >= 6.0f) ? kg - 6.0f : kg;
    float kb = i6 + 1.0f; kb = (kb >= 6.0f) ? kb - 6.0f : kb;
    r = fmaf(-c, __saturatef(fminf(kr, 4.0f - kr)), maxc);
    g = fmaf(-c, __saturatef(fminf(kg, 4.0f - kg)), maxc);
    b = fmaf(-c, __saturatef(fminf(kb, 4.0f - kb)), maxc);
}

__device__ __forceinline__ void process_quad(float4& r4, float4& g4, float4& b4,
                                             float B, float C, float cm,
                                             float S, float Hf) {
    process_px(r4.x, g4.x, b4.x, B, C, cm, S, Hf);
    process_px(r4.y, g4.y, b4.y, B, C, cm, S, Hf);
    process_px(r4.z, g4.z, b4.z, B, C, cm, S, Hf);
    process_px(r4.w, g4.w, b4.w, B, C, cm, S, Hf);
}

// Pass 2: 2 quads/thread, grid (150, nb) — exact fit. __ldcs reads (last
// touch, L2-resident from pass 1), __stcs writes (never re-read). Mean is
// broadcast via shared memory; the barrier drains the STS so the load is
// complete before this block's ticket, making the last-ticket reset safe.
__global__ void __launch_bounds__(MAIN_THREADS)
cr_main_kernel(const float* __restrict__ x,
               const float* __restrict__ bf, const float* __restrict__ cf,
               const float* __restrict__ sf, const float* __restrict__ hf,
               float* __restrict__ out, unsigned total_blocks) {
    const int b = blockIdx.y;
    const int q0 = blockIdx.x * (MAIN_THREADS * MAIN_QPT) + threadIdx.x;
    const int q1 = q0 + MAIN_THREADS;

    __shared__ float sh_m;
    if (threadIdx.x == 0) sh_m = g_graysum[b];
    __syncthreads();     // BAR drains the STS → load completed before ticket
    if (threadIdx.x == 0) {
        const unsigned ticket = atomicAdd(&g_fin, 1u);
        if (ticket == total_blocks - 1u) {
            #pragma unroll
            for (int i = 0; i < MAX_B; i++) g_graysum[i] = 0.0f;
            g_fin = 0u;
            __threadfence();
        }
    }
    const float m = sh_m * (1.0f / (float)HW);

    const float4* inb = (const float4*)(x + (size_t)b * CHW);
    float4* outb = (float4*)(out + (size_t)b * CHW);

    const float B = bf[b];
    const float C = cf[b];
    const float S = sf[b];
    const float Hf = hf[b];
    const float cm = (1.0f - C) * m;

    float4 r0 = __ldcs(&inb[q0]);
    float4 g0 = __ldcs(&inb[q0 + QPP]);
    float4 c0 = __ldcs(&inb[q0 + 2 * QPP]);
    float4 r1 = __ldcs(&inb[q1]);
    float4 g1 = __ldcs(&inb[q1 + QPP]);
    float4 c1 = __ldcs(&inb[q1 + 2 * QPP]);

    process_quad(r0, g0, c0, B, C, cm, S, Hf);
    __stcs(&outb[q0],           r0);
    __stcs(&outb[q0 + QPP],     g0);
    __stcs(&outb[q0 + 2 * QPP], c0);

    process_quad(r1, g1, c1, B, C, cm, S, Hf);
    __stcs(&outb[q1],           r1);
    __stcs(&outb[q1 + QPP],     g1);
    __stcs(&outb[q1 + 2 * QPP], c1);
}

extern "C" void kernel_launch(void* const* d_in, const int* in_sizes, int n_in,
                              void* d_out, int out_size) {
    const float* x  = (const float*)d_in[0];
    const float* bf = (const float*)d_in[1];
    const float* cf = (const float*)d_in[2];
    const float* sf = (const float*)d_in[3];
    const float* hf = (const float*)d_in[4];
    float* out = (float*)d_out;

    const int nb = out_size / CHW;  // num_samples is 1 by shape constraints

    dim3 rgrid(RED_BLOCKS_PER_PLANE, nb);
    cr_reduce_kernel<<<rgrid, RED_THREADS>>>(x, bf);

    dim3 mgrid(MAIN_BLOCKS_PER_PLANE, nb);
    cr_main_kernel<<<mgrid, MAIN_THREADS>>>(x, bf, cf, sf, hf, out,
                                            (unsigned)(MAIN_BLOCKS_PER_PLANE * nb));
}

// round 8
// speedup vs baseline: 1.0057x; 1.0057x over previous
#include <cuda_runtime.h>
#include <cuda_bf16.h>

#define IMG_H 480
#define IMG_W 640
#define HW (IMG_H * IMG_W)          // 307200
#define CHW (3 * HW)
#define QPP (HW / 4)                // float4 quads per plane = 76800
#define RED_THREADS 256
#define RED_QPT 4
#define RED_BLOCKS_PER_PLANE (QPP / (RED_THREADS * RED_QPT))   // 75, exact
#define MAIN_THREADS 256
#define MAIN_BLOCKS_PER_PLANE (QPP / MAIN_THREADS)             // 300, exact
#define MAX_B 64

// Scratch (device globals per harness rules).
// g_graysum starts zeroed (static init); the LAST main-kernel block to check
// in (after every block has read the mean) re-zeroes it for the next replay.
__device__ float g_graysum[MAX_B];
__device__ unsigned g_fin = 0;

__device__ __forceinline__ float quad_gray(const float4& r4, const float4& g4,
                                           const float4& b4, float B) {
    float s = 0.0f;
    float r, g, bl;
    #define ACC(comp) \
        r = __saturatef(r4.comp * B); \
        g = __saturatef(g4.comp * B); \
        bl = __saturatef(b4.comp * B); \
        s += 0.299f * r + 0.587f * g + 0.114f * bl;
    ACC(x) ACC(y) ACC(z) ACC(w)
    #undef ACC
    return s;
}

// Pass 1: per-batch gray sums, 4 quads/thread in two pipelined halves.
// Default cache policy so x becomes L2-resident for pass 2.
__global__ void __launch_bounds__(RED_THREADS)
cr_reduce_kernel(const float* __restrict__ x, const float* __restrict__ bf) {
    const int b = blockIdx.y;
    const int q0 = blockIdx.x * (RED_THREADS * RED_QPT) + threadIdx.x;
    const float4* base = (const float4*)(x + (size_t)b * CHW);
    const float B = bf[b];

    float s;
    {   // half 1: quads q0, q0+256 (6 loads in flight)
        const int qa = q0, qb = q0 + RED_THREADS;
        float4 r0 = base[qa], g0 = base[qa + QPP], c0 = base[qa + 2 * QPP];
        float4 r1 = base[qb], g1 = base[qb + QPP], c1 = base[qb + 2 * QPP];
        s = quad_gray(r0, g0, c0, B) + quad_gray(r1, g1, c1, B);
    }
    {   // half 2: quads q0+512, q0+768
        const int qa = q0 + 2 * RED_THREADS, qb = q0 + 3 * RED_THREADS;
        float4 r0 = base[qa], g0 = base[qa + QPP], c0 = base[qa + 2 * QPP];
        float4 r1 = base[qb], g1 = base[qb + QPP], c1 = base[qb + 2 * QPP];
        s += quad_gray(r0, g0, c0, B) + quad_gray(r1, g1, c1, B);
    }

    #pragma unroll
    for (int o = 16; o > 0; o >>= 1)
        s += __shfl_xor_sync(0xFFFFFFFFu, s, o);

    __shared__ float warp_s[RED_THREADS / 32];
    const int lane = threadIdx.x & 31;
    const int wid = threadIdx.x >> 5;
    if (lane == 0) warp_s[wid] = s;
    __syncthreads();
    if (wid == 0) {
        s = (lane < RED_THREADS / 32) ? warp_s[lane] : 0.0f;
        #pragma unroll
        for (int o = 4; o > 0; o >>= 1)
            s += __shfl_xor_sync(0xFFFFFFFFu, s, o);
        if (lane == 0) atomicAdd(&g_graysum[b], s);
    }
}

// Branchless fused pipeline. cm = (1-C)*mean is batch-uniform (hoisted).
// Hue output channels use direct ramp forms of clamp01(min(k,4-k)) with
// k = (i6 + n) mod 6 — the mod is algebraically eliminated:
//   R (n=5): clamp01(min(i6-1, 5-i6))
//   G (n=3): clamp01(max(1-i6, i6-3))
//   B (n=1): clamp01(max(3-i6, i6-5))
// (verified against the reference case table at all breakpoints incl. i6=6).
__device__ __forceinline__ void process_px(float& r, float& g, float& b,
                                           float Bf, float Cf, float cm,
                                           float Sf, float hfv) {
    // brightness
    r = __saturatef(r * Bf);
    g = __saturatef(g * Bf);
    b = __saturatef(b * Bf);
    // contrast
    r = __saturatef(fmaf(Cf, r, cm));
    g = __saturatef(fmaf(Cf, g, cm));
    b = __saturatef(fmaf(Cf, b, cm));
    // saturation
    const float gray = 0.299f * r + 0.587f * g + 0.114f * b;
    const float sm = (1.0f - Sf) * gray;
    r = __saturatef(fmaf(Sf, r, sm));
    g = __saturatef(fmaf(Sf, g, sm));
    b = __saturatef(fmaf(Sf, b, sm));
    // hue rotation — branchless (v*s == chroma identically)
    const float maxc = fmaxf(r, fmaxf(g, b));
    const float minc = fminf(r, fminf(g, b));
    const float c = maxc - minc;
    const float crd = (c == 0.0f) ? 1.0f : c;
    float num, base;
    if (maxc == r)      { num = g - b; base = 0.0f; }   // priority order kept
    else if (maxc == g) { num = b - r; base = 2.0f; }
    else                { num = r - g; base = 4.0f; }
    float h = (base + __fdividef(num, crd)) * (1.0f / 6.0f);
    h -= floorf(h);          // positive mod 1 (jnp semantics)
    h += hfv;
    h -= floorf(h);
    const float i6 = h * 6.0f;               // in [0, 6]
    const float wr = fminf(i6 - 1.0f, 5.0f - i6);
    const float wg = fmaxf(1.0f - i6, i6 - 3.0f);
    const float wb = fmaxf(3.0f - i6, i6 - 5.0f);
    r = fmaf(-c, __saturatef(wr), maxc);
    g = fmaf(-c, __saturatef(wg), maxc);
    b = fmaf(-c, __saturatef(wb), maxc);
}

// Pass 2: 1 quad/thread, grid (300, nb) — exact fit, 32 regs, full occupancy.
// __ldcs reads (last touch, L2-resident from pass 1), __stcs writes (never
// re-read). Mean broadcast via shared memory; the barrier drains the STS so
// the load completes before this block's ticket, making the last-ticket
// reset of g_graysum safe while other blocks still compute.
__global__ void __launch_bounds__(MAIN_THREADS)
cr_main_kernel(const float* __restrict__ x,
               const float* __restrict__ bf, const float* __restrict__ cf,
               const float* __restrict__ sf, const float* __restrict__ hf,
               float* __restrict__ out, unsigned total_blocks) {
    const int b = blockIdx.y;
    const int quad = blockIdx.x * MAIN_THREADS + threadIdx.x;

    __shared__ float sh_m;
    if (threadIdx.x == 0) sh_m = g_graysum[b];
    __syncthreads();     // BAR drains the STS → load completed before ticket
    if (threadIdx.x == 0) {
        const unsigned ticket = atomicAdd(&g_fin, 1u);
        if (ticket == total_blocks - 1u) {
            #pragma unroll
            for (int i = 0; i < MAX_B; i++) g_graysum[i] = 0.0f;
            g_fin = 0u;
            __threadfence();
        }
    }
    const float m = sh_m * (1.0f / (float)HW);

    const float4* inb = (const float4*)(x + (size_t)b * CHW);
    float4* outb = (float4*)(out + (size_t)b * CHW);

    const float B = bf[b];
    const float C = cf[b];
    const float S = sf[b];
    const float Hf = hf[b];
    const float cm = (1.0f - C) * m;

    float4 r4 = __ldcs(&inb[quad]);
    float4 g4 = __ldcs(&inb[quad + QPP]);
    float4 b4 = __ldcs(&inb[quad + 2 * QPP]);

    process_px(r4.x, g4.x, b4.x, B, C, cm, S, Hf);
    process_px(r4.y, g4.y, b4.y, B, C, cm, S, Hf);
    process_px(r4.z, g4.z, b4.z, B, C, cm, S, Hf);
    process_px(r4.w, g4.w, b4.w, B, C, cm, S, Hf);

    __stcs(&outb[quad],           r4);
    __stcs(&outb[quad + QPP],     g4);
    __stcs(&outb[quad + 2 * QPP], b4);
}

extern "C" void kernel_launch(void* const* d_in, const int* in_sizes, int n_in,
                              void* d_out, int out_size) {
    const float* x  = (const float*)d_in[0];
    const float* bf = (const float*)d_in[1];
    const float* cf = (const float*)d_in[2];
    const float* sf = (const float*)d_in[3];
    const float* hf = (const float*)d_in[4];
    float* out = (float*)d_out;

    const int nb = out_size / CHW;  // num_samples is 1 by shape constraints

    dim3 rgrid(RED_BLOCKS_PER_PLANE, nb);
    cr_reduce_kernel<<<rgrid, RED_THREADS>>>(x, bf);

    dim3 mgrid(MAIN_BLOCKS_PER_PLANE, nb);
    cr_main_kernel<<<mgrid, MAIN_THREADS>>>(x, bf, cf, sf, hf, out,
                                            (unsigned)(MAIN_BLOCKS_PER_PLANE * nb));
}